// round 12
// baseline (speedup 1.0000x reference)
#include <cuda_runtime.h>
#include <cuda_bf16.h>
#include <cstdint>
#include <cstddef>

// Problem dims
#define B_    2
#define T_    2048
#define C_    1024
#define H_    16
#define NH    64
#define MROWS 4096                       // B*T
constexpr size_t SLOT = (size_t)MROWS * C_;   // 4,194,304 elements per scratch slot
constexpr size_t WSLOT = (size_t)C_ * C_;     // 1,048,576 elements per weight

// Scratch slots:
// 0:xr 1:xw 2:xk 3:xv 4:xa 5:xg
// 6:r 7:k 8:v 9:w1(tanh'd) 10:a1 11:v1 12:g1(sigmoid'd)
// 13:w(decayed) 14:DP(decay products) 15:{SL,DF,SI} 16:g 17:y 18:z
// then 12 tf32-rounded weight copies
__device__ float g_scratch[19ull * 4194304ull + 12ull * 1048576ull];

// offsets inside slot 15
#define SL_OFF 0           // Slocal: 3 segs x 32 bh x 64 x 64
#define DF_OFF 524288      // Dfull:  segs 1..2 x 32 bh x 64
#define SI_OFF 589824      // Sinit:  segs 1..3 x 32 bh x 64 x 64

__device__ __forceinline__ float sigm(float x) { return 1.0f / (1.0f + expf(-x)); }
__device__ __forceinline__ float rtf(float x) {
    float r; asm("cvt.rna.tf32.f32 %0, %1;" : "=f"(r) : "f"(x)); return r;
}
__device__ __forceinline__ float4 rtf4(float4 v) {
    return make_float4(rtf(v.x), rtf(v.y), rtf(v.z), rtf(v.w));
}

__device__ __forceinline__ uint32_t smem_u32(const void* p) {
    uint32_t a;
    asm("{ .reg .u64 t; cvta.to.shared.u64 t, %1; cvt.u32.u64 %0, t; }" : "=r"(a) : "l"(p));
    return a;
}
__device__ __forceinline__ void cp_async16(uint32_t s, const void* g) {
    asm volatile("cp.async.ca.shared.global [%0], [%1], 16;\n" :: "r"(s), "l"(g));
}
__device__ __forceinline__ void cp_commit() { asm volatile("cp.async.commit_group;\n"); }
template <int Nn> __device__ __forceinline__ void cp_wait() {
    asm volatile("cp.async.wait_group %0;\n" :: "n"(Nn));
}

// ---------------------------------------------------------------------------
// K0: one-time tf32 rounding of the 12 weight matrices
// ---------------------------------------------------------------------------
struct Ptr12 { const float* p[12]; };

__global__ __launch_bounds__(256) void wcvt_kernel(Ptr12 ws, float* __restrict__ out)
{
    int w  = blockIdx.y;
    int e4 = blockIdx.x * 256 + threadIdx.x;   // 0..262143
    float4 v = reinterpret_cast<const float4*>(ws.p[w])[e4];
    reinterpret_cast<float4*>(out + (size_t)w * WSLOT)[e4] = rtf4(v);
}

// ---------------------------------------------------------------------------
// K1: token-shift mixing — 6 tf32-rounded outputs from one pass over x
// ---------------------------------------------------------------------------
__global__ __launch_bounds__(256) void mix_kernel(
    const float* __restrict__ X,
    const float* __restrict__ tmr, const float* __restrict__ tmw,
    const float* __restrict__ tmk, const float* __restrict__ tmv,
    const float* __restrict__ tma, const float* __restrict__ tmg,
    float* __restrict__ buf)
{
    const int NC4 = C_ / 4;
    int e4 = blockIdx.x * 256 + threadIdx.x;
    if (e4 >= MROWS * NC4) return;
    int m  = e4 / NC4;
    int c4 = e4 - m * NC4;
    int t  = m & (T_ - 1);

    const float4* X4 = reinterpret_cast<const float4*>(X);
    float4 xc = X4[e4];
    float4 xp = make_float4(0.f, 0.f, 0.f, 0.f);
    if (t != 0) xp = X4[e4 - NC4];
    float4 xx = make_float4(xp.x - xc.x, xp.y - xc.y, xp.z - xc.z, xp.w - xc.w);

    float4* out = reinterpret_cast<float4*>(buf);
    const float* tms[6] = {tmr, tmw, tmk, tmv, tma, tmg};
#pragma unroll
    for (int s = 0; s < 6; s++) {
        float4 tm = reinterpret_cast<const float4*>(tms[s])[c4];
        float4 o = make_float4(xc.x + xx.x * tm.x, xc.y + xx.y * tm.y,
                               xc.z + xx.z * tm.z, xc.w + xx.w * tm.w);
        out[(size_t)s * (SLOT / 4) + e4] = rtf4(o);
    }
}

// ---------------------------------------------------------------------------
// K2: hand-rolled TF32 mma GEMM (exact R7 config: BK=32, 2-stage, 64x64 warp
// tile, fused epilogues).  out[m,n] = sum_k A[m,k] * W[n,k]
// Epilogue act: 0 none, 1 tanh+round, 2 sigmoid+round, 3 round,
//               4 w-decay(aux1=w0), 5 k-adjust rmw(aux1=a0,aux2=k_a),
//               6 v-blend rmw(aux1=v0,aux2=v_first)
// ---------------------------------------------------------------------------
#define BMG 128
#define BNG 128
#define BKG 32
#define NKT (C_ / BKG)        // 32
#define RS  36                // padded row stride in floats (32 + 4)
#define AST (128 * RS)        // floats per matrix tile per stage (4608)
#define STF (2 * AST)         // floats per stage (9216)
constexpr int GEMM_SMEM = 2 * STF * 4;   // 73728 bytes

struct GemmItem {
    const float* A; const float* W; float* O; int act;
    const float* aux1; const float* aux2;
};
struct GemmBatch7 { GemmItem it[7]; };

#define MMA_TF32(d, a, b) \
    asm volatile( \
        "mma.sync.aligned.m16n8k8.row.col.f32.tf32.tf32.f32 " \
        "{%0,%1,%2,%3}, {%4,%5,%6,%7}, {%8,%9}, {%0,%1,%2,%3};" \
        : "+f"((d)[0]), "+f"((d)[1]), "+f"((d)[2]), "+f"((d)[3]) \
        : "r"((a)[0]), "r"((a)[1]), "r"((a)[2]), "r"((a)[3]), \
          "r"((b)[0]), "r"((b)[1]))

extern __shared__ float smg[];

__global__ __launch_bounds__(128, 2) void gemm_mma_kernel(GemmBatch7 bt)
{
    const GemmItem gi = bt.it[blockIdx.z];
    const int tid  = threadIdx.x;
    const int lane = tid & 31;
    const int warpId = tid >> 5;
    const int wm = warpId & 1;            // 2 warps along M
    const int wn = warpId >> 1;           // 2 warps along N
    const int rw = wm * 64, cw = wn * 64;
    const int gid = lane >> 2;            // groupID 0..7
    const int tig = lane & 3;             // thread-in-group 0..3

    const int bm = blockIdx.y, bn = blockIdx.x;
    const float* Ab = gi.A + (size_t)bm * BMG * C_;
    const float* Wb = gi.W + (size_t)bn * BNG * C_;

    const uint32_t smb = smem_u32(smg);
    const uint32_t* smU = reinterpret_cast<const uint32_t*>(smg);

    auto load_stage = [&](int s, int kt) {
        uint32_t sb = smb + s * (STF * 4);
        int k0 = kt * BKG;
#pragma unroll
        for (int i = 0; i < 8; i++) {
            int f = tid + i * 128;        // 0..1023
            int row = f >> 3;
            int ch  = f & 7;
            cp_async16(sb + row * (RS * 4) + ch * 16,
                       Ab + (size_t)row * C_ + k0 + ch * 4);
            cp_async16(sb + AST * 4 + row * (RS * 4) + ch * 16,
                       Wb + (size_t)row * C_ + k0 + ch * 4);
        }
        cp_commit();
    };

    float acc[32][4];
#pragma unroll
    for (int i = 0; i < 32; i++)
#pragma unroll
        for (int j = 0; j < 4; j++) acc[i][j] = 0.0f;

    uint32_t af[2][16], bf[2][16];

    load_stage(0, 0);
    load_stage(1, 1);

    for (int kt = 0; kt < NKT; kt++) {
        const int s = kt & 1;
        if (kt + 1 < NKT) cp_wait<1>(); else cp_wait<0>();
        __syncthreads();

        const int sbase = s * STF;
        const int aoff = sbase + (rw + gid) * RS + tig;
        const int boff = sbase + AST + (cw + gid) * RS + tig;

        auto ldA = [&](int buf, int kk) {
#pragma unroll
            for (int mt = 0; mt < 4; mt++) {
                int base = aoff + mt * (16 * RS) + kk * 8;
                af[buf][mt*4+0] = smU[base];
                af[buf][mt*4+1] = smU[base + 8 * RS];
                af[buf][mt*4+2] = smU[base + 4];
                af[buf][mt*4+3] = smU[base + 8 * RS + 4];
            }
        };
        auto ldB = [&](int buf, int kk) {
#pragma unroll
            for (int nt = 0; nt < 8; nt++) {
                int base = boff + nt * (8 * RS) + kk * 8;
                bf[buf][nt*2+0] = smU[base];
                bf[buf][nt*2+1] = smU[base + 4];
            }
        };

        ldA(0, 0); ldB(0, 0);
        int pb = 0;
#pragma unroll
        for (int kk = 0; kk < 4; kk++) {
            if (kk < 3) { ldA(pb ^ 1, kk + 1); ldB(pb ^ 1, kk + 1); }
#pragma unroll
            for (int mt = 0; mt < 4; mt++)
#pragma unroll
                for (int nt = 0; nt < 8; nt++)
                    MMA_TF32(acc[mt*8+nt], af[pb] + mt*4, bf[pb] + nt*2);
            pb ^= 1;
        }

        __syncthreads();                 // all warps done reading stage s
        if (kt + 2 < NKT) load_stage(s, kt + 2);
    }

    // Epilogue
    const int act = gi.act;
    float* O = gi.O;
    const float* aux1 = gi.aux1;
    const float* aux2 = gi.aux2;
#pragma unroll
    for (int mt = 0; mt < 4; mt++) {
        int r0 = bm * BMG + rw + mt * 16 + gid;
#pragma unroll
        for (int nt = 0; nt < 8; nt++) {
            int col = bn * BNG + cw + nt * 8 + tig * 2;
            float v0 = acc[mt*8+nt][0], v1 = acc[mt*8+nt][1];
            float v2 = acc[mt*8+nt][2], v3 = acc[mt*8+nt][3];
            float* p0 = O + (size_t)r0 * C_ + col;
            float* p1 = O + (size_t)(r0 + 8) * C_ + col;
            if (act == 1) {
                v0 = rtf(tanhf(v0)); v1 = rtf(tanhf(v1));
                v2 = rtf(tanhf(v2)); v3 = rtf(tanhf(v3));
            } else if (act == 2) {
                v0 = rtf(sigm(v0)); v1 = rtf(sigm(v1));
                v2 = rtf(sigm(v2)); v3 = rtf(sigm(v3));
            } else if (act == 3) {
                v0 = rtf(v0); v1 = rtf(v1); v2 = rtf(v2); v3 = rtf(v3);
            } else if (act == 4) {
                float c0 = aux1[col], c1 = aux1[col + 1];
                v0 = expf(-0.606531f * sigm(c0 + v0));
                v1 = expf(-0.606531f * sigm(c1 + v1));
                v2 = expf(-0.606531f * sigm(c0 + v2));
                v3 = expf(-0.606531f * sigm(c1 + v3));
            } else if (act == 5) {
                float c0 = aux1[col], c1 = aux1[col + 1];
                float ka0 = aux2[col], ka1 = aux2[col + 1];
                float2 k0v = *reinterpret_cast<float2*>(p0);
                float2 k1v = *reinterpret_cast<float2*>(p1);
                v0 = k0v.x * (1.0f + (sigm(c0 + v0) - 1.0f) * ka0);
                v1 = k0v.y * (1.0f + (sigm(c1 + v1) - 1.0f) * ka1);
                v2 = k1v.x * (1.0f + (sigm(c0 + v2) - 1.0f) * ka0);
                v3 = k1v.y * (1.0f + (sigm(c1 + v3) - 1.0f) * ka1);
            } else if (act == 6) {
                float c0 = aux1[col], c1 = aux1[col + 1];
                const float* q0 = aux2 + (size_t)r0 * C_ + col;
                const float* q1 = aux2 + (size_t)(r0 + 8) * C_ + col;
                float2 vv0 = *reinterpret_cast<float2*>(p0);
                float2 vv1 = *reinterpret_cast<float2*>(p1);
                float2 vf0 = *reinterpret_cast<const float2*>(q0);
                float2 vf1 = *reinterpret_cast<const float2*>(q1);
                v0 = vv0.x + (vf0.x - vv0.x) * sigm(c0 + v0);
                v1 = vv0.y + (vf0.y - vv0.y) * sigm(c1 + v1);
                v2 = vv1.x + (vf1.x - vv1.x) * sigm(c0 + v2);
                v3 = vv1.y + (vf1.y - vv1.y) * sigm(c1 + v3);
            }
            *reinterpret_cast<float2*>(p0) = make_float2(v0, v1);
            *reinterpret_cast<float2*>(p1) = make_float2(v2, v3);
        }
    }
}

// ---------------------------------------------------------------------------
// K6: WKV-7 segmented scan. 4 segments of 512 steps scanned in parallel from
// zero state. Records dp (running row decay product, segs>=1), Slocal end
// state (segs<3) and Dfull (segs 1,2). grid 512 = bh(32) x rg(4) x seg(4).
// ---------------------------------------------------------------------------
#define NSEG 4
#define SEGT (T_ / NSEG)          // 512
#define WCH 8                     // timesteps per chunk
#define NCHUNK_SEG (SEGT / WCH)   // 64
#define RB_OFF 0
#define VB_OFF 1024
#define WB_OFF 2048
#define KB_OFF 2304
#define WKV_SMEM_FLOATS 2560

__global__ __launch_bounds__(128) void wkv_kernel(
    const float* __restrict__ R, const float* __restrict__ Wd,
    const float* __restrict__ K, const float* __restrict__ V,
    float* __restrict__ Y, float* __restrict__ DP,
    float* __restrict__ SL, float* __restrict__ DF)
{
    __shared__ float sm[WKV_SMEM_FLOATS];

    const int bx  = blockIdx.x;
    const int seg = bx & 3;
    const int rg  = (bx >> 2) & 3;
    const int bh  = bx >> 4;               // 0..31
    const int b   = bh >> 4;
    const int h   = bh & 15;
    const int tid = threadIdx.x;
    const int il  = tid >> 3;              // local row 0..15
    const int jq  = tid & 7;               // j-slice (8 cols)
    const int i   = rg * 16 + il;          // head-local row 0..63
    const int tseg = seg * SEGT;
    const size_t base = ((size_t)b * T_) * C_ + (size_t)h * NH;

    const uint32_t smb = smem_u32(sm);

    auto load_chunk = [&](int buf, int c) {
        int t0 = tseg + c * WCH;
        int s   = tid >> 4;
        int seg2i = tid & 15;
        const float* rs = R + base + (size_t)(t0 + s) * C_ + seg2i * 4;
        const float* vs = V + base + (size_t)(t0 + s) * C_ + seg2i * 4;
        cp_async16(smb + (RB_OFF + buf * 512 + s * 64 + seg2i * 4) * 4, rs);
        cp_async16(smb + (VB_OFF + buf * 512 + s * 64 + seg2i * 4) * 4, vs);
        if (tid < 32) {
            int s2 = tid >> 2, sg = tid & 3;
            cp_async16(smb + (WB_OFF + buf * 128 + s2 * 16 + sg * 4) * 4,
                       Wd + base + (size_t)(t0 + s2) * C_ + rg * 16 + sg * 4);
        } else if (tid < 64) {
            int t2 = tid - 32;
            int s2 = t2 >> 2, sg = t2 & 3;
            cp_async16(smb + (KB_OFF + buf * 128 + s2 * 16 + sg * 4) * 4,
                       K + base + (size_t)(t0 + s2) * C_ + rg * 16 + sg * 4);
        }
        cp_commit();
    };

    float S[8];
#pragma unroll
    for (int u = 0; u < 8; u++) S[u] = 0.0f;
    float dpreg = 1.0f;

    load_chunk(0, 0);
    load_chunk(1, 1);

    for (int c = 0; c < NCHUNK_SEG; c++) {
        const int buf = c & 1;
        if (c + 1 < NCHUNK_SEG) cp_wait<1>(); else cp_wait<0>();
        __syncthreads();

        const float* rb = sm + RB_OFF + buf * 512;
        const float* vb = sm + VB_OFF + buf * 512;
        const float* wb = sm + WB_OFF + buf * 128;
        const float* kb = sm + KB_OFF + buf * 128;

#pragma unroll
        for (int s = 0; s < WCH; s++) {
            float4 r0 = *reinterpret_cast<const float4*>(rb + s * 64 + jq * 8);
            float4 r1 = *reinterpret_cast<const float4*>(rb + s * 64 + jq * 8 + 4);
            float4 v0 = *reinterpret_cast<const float4*>(vb + s * 64 + jq * 8);
            float4 v1 = *reinterpret_cast<const float4*>(vb + s * 64 + jq * 8 + 4);
            const float wi = wb[s * 16 + il];
            const float ki = kb[s * 16 + il];

            dpreg *= wi;

            float a0 = 0.f, a1 = 0.f;
            float t0v = S[0] * wi + ki * v0.x; S[0] = t0v; a0 += t0v * r0.x;
            float t1v = S[1] * wi + ki * v0.y; S[1] = t1v; a1 += t1v * r0.y;
            float t2v = S[2] * wi + ki * v0.z; S[2] = t2v; a0 += t2v * r0.z;
            float t3v = S[3] * wi + ki * v0.w; S[3] = t3v; a1 += t3v * r0.w;
            float t4v = S[4] * wi + ki * v1.x; S[4] = t4v; a0 += t4v * r1.x;
            float t5v = S[5] * wi + ki * v1.y; S[5] = t5v; a1 += t5v * r1.y;
            float t6v = S[6] * wi + ki * v1.z; S[6] = t6v; a0 += t6v * r1.z;
            float t7v = S[7] * wi + ki * v1.w; S[7] = t7v; a1 += t7v * r1.w;

            float red = a0 + a1;
            red += __shfl_xor_sync(0xffffffffu, red, 1);
            red += __shfl_xor_sync(0xffffffffu, red, 2);
            red += __shfl_xor_sync(0xffffffffu, red, 4);
            const size_t ti = base + (size_t)(tseg + c * WCH + s) * C_ + i;
            if (jq == 0) {
                Y[ti] = red;
                if (seg > 0) DP[ti] = dpreg;
            }
        }

        __syncthreads();
        if (c + 2 < NCHUNK_SEG) load_chunk(buf, c + 2);
        else cp_commit();
    }

    // save segment-final local state + full-segment decay
    if (seg < 3) {
        float* slp = SL + (((size_t)seg * 32 + bh) * 64 + i) * 64 + jq * 8;
        *reinterpret_cast<float4*>(slp)     = make_float4(S[0], S[1], S[2], S[3]);
        *reinterpret_cast<float4*>(slp + 4) = make_float4(S[4], S[5], S[6], S[7]);
        if (seg >= 1 && jq == 0)
            DF[((size_t)seg * 32 + bh) * 64 + i] = dpreg;
    }
}

// ---------------------------------------------------------------------------
// K6b: combine segment states:  Sinit[s+1] = Dfull[s] (.) Sinit[s] + Slocal[s]
// grid 32 (bh), 256 threads.
// ---------------------------------------------------------------------------
__global__ __launch_bounds__(256) void wkv_combine_kernel(
    const float* __restrict__ SL, const float* __restrict__ DF,
    float* __restrict__ SI)
{
    const int bh  = blockIdx.x;
    const int tid = threadIdx.x;
#pragma unroll
    for (int q = 0; q < 4; q++) {
        int idx4 = tid + q * 256;            // 0..1023 (float4 index in 64x64)
        int i = idx4 >> 4;                   // row
        const float4* Sl0 = reinterpret_cast<const float4*>(SL + ((size_t)0 * 32 + bh) * 4096);
        const float4* Sl1 = reinterpret_cast<const float4*>(SL + ((size_t)1 * 32 + bh) * 4096);
        const float4* Sl2 = reinterpret_cast<const float4*>(SL + ((size_t)2 * 32 + bh) * 4096);
        float4* Si0 = reinterpret_cast<float4*>(SI + ((size_t)0 * 32 + bh) * 4096);
        float4* Si1 = reinterpret_cast<float4*>(SI + ((size_t)1 * 32 + bh) * 4096);
        float4* Si2 = reinterpret_cast<float4*>(SI + ((size_t)2 * 32 + bh) * 4096);

        float4 si = Sl0[idx4];               // Sinit for segment 1
        Si0[idx4] = si;

        float d1 = DF[((size_t)1 * 32 + bh) * 64 + i];
        float4 s1 = Sl1[idx4];
        si = make_float4(d1 * si.x + s1.x, d1 * si.y + s1.y,
                         d1 * si.z + s1.z, d1 * si.w + s1.w);   // Sinit for seg 2
        Si1[idx4] = si;

        float d2 = DF[((size_t)2 * 32 + bh) * 64 + i];
        float4 s2 = Sl2[idx4];
        si = make_float4(d2 * si.x + s2.x, d2 * si.y + s2.y,
                         d2 * si.z + s2.z, d2 * si.w + s2.w);   // Sinit for seg 3
        Si2[idx4] = si;
    }
}

// ---------------------------------------------------------------------------
// K6c: correction  y[t in seg s] += dp_t (.) (Sinit[s] . r_t)
// grid 96 = s(3) x bh(32), 256 threads. Sinit staged in smem (padded).
// ---------------------------------------------------------------------------
__global__ __launch_bounds__(256) void wkv_corr_kernel(
    const float* __restrict__ R, const float* __restrict__ DP,
    const float* __restrict__ SI, float* __restrict__ Y)
{
    __shared__ float4 Ssm[64 * 17];
    __shared__ float4 rwin[16 * 16];

    const int s  = blockIdx.x >> 5;      // 0..2  -> segment s+1
    const int bh = blockIdx.x & 31;
    const int b  = bh >> 4;
    const int h  = bh & 15;
    const int tid = threadIdx.x;

    const float4* SI4 = reinterpret_cast<const float4*>(SI + ((size_t)s * 32 + bh) * 4096);
#pragma unroll
    for (int q = 0; q < 4; q++) {
        int idx4 = tid + q * 256;
        int i  = idx4 >> 4;
        int j4 = idx4 & 15;
        Ssm[i * 17 + j4] = SI4[idx4];
    }
    __syncthreads();

    const int i  = tid & 63;
    const int tg = tid >> 6;             // 0..3
    const size_t base = ((size_t)b * T_) * C_ + (size_t)h * NH;
    const int t0 = (s + 1) * SEGT;

    for (int tw = 0; tw < SEGT; tw += 16) {
        {
            int tt = tid >> 4, j4 = tid & 15;
            rwin[tt * 16 + j4] =
                reinterpret_cast<const float4*>(R + base + (size_t)(t0 + tw + tt) * C_)[j4];
        }
        __syncthreads();
#pragma unroll
        for (int tt = tg; tt < 16; tt += 4) {
            float a0 = 0.f, a1 = 0.f, a2 = 0.f, a3 = 0.f;
#pragma unroll
            for (int j4 = 0; j4 < 16; j4++) {
                float4 sv = Ssm[i * 17 + j4];
                float4 rv = rwin[tt * 16 + j4];
                a0 += sv.x * rv.x; a1 += sv.y * rv.y;
                a2 += sv.z * rv.z; a3 += sv.w * rv.w;
            }
            float acc = (a0 + a1) + (a2 + a3);
            size_t yi = base + (size_t)(t0 + tw + tt) * C_ + i;
            Y[yi] += DP[yi] * acc;
        }
        __syncthreads();
    }
}

// ---------------------------------------------------------------------------
// K7: LayerNorm(C) + rkv residual + gate:  z = (LN(y) + rkv) * g   (tf32 out)
// ---------------------------------------------------------------------------
__global__ __launch_bounds__(256) void ln_gate_kernel(
    const float* __restrict__ Yb, const float* __restrict__ Rb, const float* __restrict__ Kb,
    const float* __restrict__ Vb, const float* __restrict__ Gb,
    const float* __restrict__ rk, const float* __restrict__ lng, const float* __restrict__ lnb,
    float* __restrict__ Zb)
{
    const int m = blockIdx.x;
    const size_t base = (size_t)m * C_;
    __shared__ float sprod[C_];
    __shared__ float hdot[H_];
    __shared__ float rs[8], rq[8], stats[2];

    const int tid = threadIdx.x;
    float yv[4];
    float lsum = 0.f, lsq = 0.f;
#pragma unroll
    for (int u = 0; u < 4; u++) {
        int c = tid + u * 256;
        float t = Yb[base + c];
        yv[u] = t; lsum += t; lsq += t * t;
        sprod[c] = Rb[base + c] * Kb[base + c] * rk[c];
    }
#pragma unroll
    for (int o = 16; o > 0; o >>= 1) {
        lsum += __shfl_xor_sync(0xffffffffu, lsum, o);
        lsq  += __shfl_xor_sync(0xffffffffu, lsq,  o);
    }
    if ((tid & 31) == 0) { rs[tid >> 5] = lsum; rq[tid >> 5] = lsq; }
    __syncthreads();
    if (tid == 0) {
        float sv = 0.f, qv = 0.f;
        for (int wq = 0; wq < 8; wq++) { sv += rs[wq]; qv += rq[wq]; }
        float mu = sv / (float)C_;
        stats[0] = mu;
        stats[1] = rsqrtf(qv / (float)C_ - mu * mu + 1e-5f);
    }
    if (tid < 16) {
        float d = 0.f;
        for (int n = 0; n < 64; n++) d += sprod[tid * 64 + n];
        hdot[tid] = d;
    }
    __syncthreads();
    const float mu = stats[0], rstd = stats[1];
#pragma unroll
    for (int u = 0; u < 4; u++) {
        int c = tid + u * 256;
        int hh = c >> 6;
        float z = ((yv[u] - mu) * rstd * lng[c] + lnb[c] + hdot[hh] * Vb[base + c]) * Gb[base + c];
        Zb[base + c] = rtf(z);
    }
}

// ---------------------------------------------------------------------------
// Launcher
// ---------------------------------------------------------------------------
extern "C" void kernel_launch(void* const* d_in, const int* in_sizes, int n_in,
                              void* d_out, int out_size)
{
    (void)in_sizes; (void)n_in; (void)out_size;
    const float* x       = (const float*)d_in[0];
    const float* v_first = (const float*)d_in[1];
    const float* Wr  = (const float*)d_in[2];
    const float* Wk  = (const float*)d_in[3];
    const float* Wv  = (const float*)d_in[4];
    const float* Wo  = (const float*)d_in[5];
    const float* Wg1 = (const float*)d_in[6];
    const float* Wg2 = (const float*)d_in[7];
    const float* W1  = (const float*)d_in[8];
    const float* W2  = (const float*)d_in[9];
    const float* A1  = (const float*)d_in[10];
    const float* A2  = (const float*)d_in[11];
    const float* V1  = (const float*)d_in[12];
    const float* V2  = (const float*)d_in[13];
    const float* tm_r = (const float*)d_in[14];
    const float* tm_w = (const float*)d_in[15];
    const float* tm_k = (const float*)d_in[16];
    const float* tm_v = (const float*)d_in[17];
    const float* tm_a = (const float*)d_in[18];
    const float* tm_g = (const float*)d_in[19];
    const float* w0  = (const float*)d_in[20];
    const float* a0  = (const float*)d_in[21];
    const float* v0  = (const float*)d_in[22];
    const float* k_a = (const float*)d_in[24];
    const float* r_k = (const float*)d_in[25];
    const float* ln_g = (const float*)d_in[26];
    const float* ln_b = (const float*)d_in[27];

    float* buf = nullptr;
    cudaGetSymbolAddress((void**)&buf, g_scratch);
    auto S  = [&](int s) { return buf + (size_t)s * SLOT; };
    float* wbase = buf + 19 * SLOT;
    auto WB = [&](int w) { return (const float*)(wbase + (size_t)w * WSLOT); };

    float* DP = S(14);
    float* SL = S(15) + SL_OFF;
    float* DF = S(15) + DF_OFF;
    float* SI = S(15) + SI_OFF;

    cudaFuncSetAttribute((const void*)gemm_mma_kernel,
                         cudaFuncAttributeMaxDynamicSharedMemorySize, GEMM_SMEM);

    const int EW_BLOCKS = MROWS * C_ / 4 / 256;   // 4096
    dim3 gg(C_ / BNG, MROWS / BMG);               // (8, 32)

    // K0: tf32-round the weights
    Ptr12 ws;
    ws.p[0] = Wr;  ws.p[1] = Wk;  ws.p[2] = Wv;  ws.p[3] = W1;
    ws.p[4] = A1;  ws.p[5] = V1;  ws.p[6] = Wg1; ws.p[7] = W2;
    ws.p[8] = A2;  ws.p[9] = V2;  ws.p[10] = Wg2; ws.p[11] = Wo;
    wcvt_kernel<<<dim3(1024, 12), 256>>>(ws, wbase);

    // K1: token-shift mixes -> slots 0..5, tf32-rounded
    mix_kernel<<<EW_BLOCKS, 256>>>(x, tm_r, tm_w, tm_k, tm_v, tm_a, tm_g, buf);

    // Stage-1 batched GEMMs (7)
    GemmBatch7 b1;
    b1.it[0] = { S(0), WB(0), S(6),  0, nullptr, nullptr };   // r
    b1.it[1] = { S(2), WB(1), S(7),  0, nullptr, nullptr };   // k
    b1.it[2] = { S(3), WB(2), S(8),  0, nullptr, nullptr };   // v
    b1.it[3] = { S(1), WB(3), S(9),  1, nullptr, nullptr };   // w1 = tanh(.)
    b1.it[4] = { S(4), WB(4), S(10), 3, nullptr, nullptr };   // a1
    b1.it[5] = { S(3), WB(5), S(11), 3, nullptr, nullptr };   // v1
    b1.it[6] = { S(5), WB(6), S(12), 2, nullptr, nullptr };   // g1 = sigmoid(.)
    gemm_mma_kernel<<<dim3(gg.x, gg.y, 7), 128, GEMM_SMEM>>>(b1);

    // Stage-2 batched GEMMs (4) with fused ew2 epilogues
    GemmBatch7 b2;
    b2.it[0] = { S(9),  WB(7),  S(13), 4, w0,  nullptr };   // w = exp(-.6*sig(w0+.))
    b2.it[1] = { S(10), WB(8),  S(7),  5, a0,  k_a     };   // k-adjust (rmw k)
    b2.it[2] = { S(11), WB(9),  S(8),  6, v0,  v_first };   // v-blend (rmw v)
    b2.it[3] = { S(12), WB(10), S(16), 0, nullptr, nullptr }; // g
    gemm_mma_kernel<<<dim3(gg.x, gg.y, 4), 128, GEMM_SMEM>>>(b2);

    // K6: segmented WKV scan -> y_local (+ dp, Slocal, Dfull)
    wkv_kernel<<<512, 128>>>(S(6), S(13), S(7), S(8), S(17), DP, SL, DF);

    // K6b: cascade segment initial states
    wkv_combine_kernel<<<32, 256>>>(SL, DF, SI);

    // K6c: add cross-segment correction to y
    wkv_corr_kernel<<<96, 256>>>(S(6), DP, SI, S(17));

    // K7: LN + rkv + gate -> z, tf32-rounded
    ln_gate_kernel<<<MROWS, 256>>>(S(17), S(6), S(7), S(8), S(16),
                                   r_k, ln_g, ln_b, S(18));

    // Final GEMM: out = z @ Wo^T
    GemmBatch7 b3;
    b3.it[0] = { S(18), WB(11), (float*)d_out, 0, nullptr, nullptr };
    gemm_mma_kernel<<<dim3(gg.x, gg.y, 1), 128, GEMM_SMEM>>>(b3);
}

// round 16
// speedup vs baseline: 1.1116x; 1.1116x over previous
#include <cuda_runtime.h>
#include <cuda_bf16.h>
#include <cstdint>
#include <cstddef>

// Problem dims
#define B_    2
#define T_    2048
#define C_    1024
#define H_    16
#define NH    64
#define MROWS 4096                       // B*T
constexpr size_t SLOT = (size_t)MROWS * C_;   // 4,194,304 elements per scratch slot
constexpr size_t WSLOT = (size_t)C_ * C_;     // 1,048,576 elements per weight

// Scratch slots:
// 0:xr 1:xw 2:xk 3:xv 4:xa 5:xg
// 6:r 7:k 8:v 9:w1(tanh'd) 10:a1 11:v1 12:g1(sigmoid'd)
// 13:w2raw(->w) 14:a2raw 15:v2raw 16:g 17:y 18:z
// then 12 tf32-rounded weight copies
__device__ float g_scratch[19ull * 4194304ull + 12ull * 1048576ull];

__device__ __forceinline__ float sigm(float x) { return 1.0f / (1.0f + expf(-x)); }
__device__ __forceinline__ float rtf(float x) {
    float r; asm("cvt.rna.tf32.f32 %0, %1;" : "=f"(r) : "f"(x)); return r;
}
__device__ __forceinline__ float4 rtf4(float4 v) {
    return make_float4(rtf(v.x), rtf(v.y), rtf(v.z), rtf(v.w));
}

__device__ __forceinline__ uint32_t smem_u32(const void* p) {
    uint32_t a;
    asm("{ .reg .u64 t; cvta.to.shared.u64 t, %1; cvt.u32.u64 %0, t; }" : "=r"(a) : "l"(p));
    return a;
}
__device__ __forceinline__ void cp_async16(uint32_t s, const void* g) {
    asm volatile("cp.async.ca.shared.global [%0], [%1], 16;\n" :: "r"(s), "l"(g));
}
__device__ __forceinline__ void cp_commit() { asm volatile("cp.async.commit_group;\n"); }
template <int Nn> __device__ __forceinline__ void cp_wait() {
    asm volatile("cp.async.wait_group %0;\n" :: "n"(Nn));
}

// ---------------------------------------------------------------------------
// K0: one-time tf32 rounding of the 12 weight matrices
// ---------------------------------------------------------------------------
struct Ptr12 { const float* p[12]; };

__global__ __launch_bounds__(256) void wcvt_kernel(Ptr12 ws, float* __restrict__ out)
{
    int w  = blockIdx.y;
    int e4 = blockIdx.x * 256 + threadIdx.x;   // 0..262143
    float4 v = reinterpret_cast<const float4*>(ws.p[w])[e4];
    reinterpret_cast<float4*>(out + (size_t)w * WSLOT)[e4] = rtf4(v);
}

// ---------------------------------------------------------------------------
// K1: token-shift mixing — 6 tf32-rounded outputs from one pass over x
// ---------------------------------------------------------------------------
__global__ __launch_bounds__(256) void mix_kernel(
    const float* __restrict__ X,
    const float* __restrict__ tmr, const float* __restrict__ tmw,
    const float* __restrict__ tmk, const float* __restrict__ tmv,
    const float* __restrict__ tma, const float* __restrict__ tmg,
    float* __restrict__ buf)
{
    const int NC4 = C_ / 4;
    int e4 = blockIdx.x * 256 + threadIdx.x;
    if (e4 >= MROWS * NC4) return;
    int m  = e4 / NC4;
    int c4 = e4 - m * NC4;
    int t  = m & (T_ - 1);

    const float4* X4 = reinterpret_cast<const float4*>(X);
    float4 xc = X4[e4];
    float4 xp = make_float4(0.f, 0.f, 0.f, 0.f);
    if (t != 0) xp = X4[e4 - NC4];
    float4 xx = make_float4(xp.x - xc.x, xp.y - xc.y, xp.z - xc.z, xp.w - xc.w);

    float4* out = reinterpret_cast<float4*>(buf);
    const float* tms[6] = {tmr, tmw, tmk, tmv, tma, tmg};
#pragma unroll
    for (int s = 0; s < 6; s++) {
        float4 tm = reinterpret_cast<const float4*>(tms[s])[c4];
        float4 o = make_float4(xc.x + xx.x * tm.x, xc.y + xx.y * tm.y,
                               xc.z + xx.z * tm.z, xc.w + xx.w * tm.w);
        out[(size_t)s * (SLOT / 4) + e4] = rtf4(o);
    }
}

// ---------------------------------------------------------------------------
// K2: hand-rolled TF32 mma GEMM (R5-measured-best config: BK=32, 2-stage,
// 4 warps 2Mx2N, warp tile 64x64, register double-buffered fragments,
// LIGHT epilogues only).  out[m,n] = sum_k A[m,k] * W[n,k]
// Epilogue act: 0 none, 1 tanh+round, 2 sigmoid+round, 3 round.
// ---------------------------------------------------------------------------
#define BMG 128
#define BNG 128
#define BKG 32
#define NKT (C_ / BKG)        // 32
#define RS  36                // padded row stride in floats (32 + 4)
#define AST (128 * RS)        // floats per matrix tile per stage (4608)
#define STF (2 * AST)         // floats per stage (9216)
constexpr int GEMM_SMEM = 2 * STF * 4;   // 73728 bytes

struct GemmItem { const float* A; const float* W; float* O; int act; };
struct GemmBatch7 { GemmItem it[7]; };

#define MMA_TF32(d, a, b) \
    asm volatile( \
        "mma.sync.aligned.m16n8k8.row.col.f32.tf32.tf32.f32 " \
        "{%0,%1,%2,%3}, {%4,%5,%6,%7}, {%8,%9}, {%0,%1,%2,%3};" \
        : "+f"((d)[0]), "+f"((d)[1]), "+f"((d)[2]), "+f"((d)[3]) \
        : "r"((a)[0]), "r"((a)[1]), "r"((a)[2]), "r"((a)[3]), \
          "r"((b)[0]), "r"((b)[1]))

extern __shared__ float smg[];

__global__ __launch_bounds__(128, 2) void gemm_mma_kernel(GemmBatch7 bt)
{
    const GemmItem gi = bt.it[blockIdx.z];
    const int tid  = threadIdx.x;
    const int lane = tid & 31;
    const int warpId = tid >> 5;
    const int wm = warpId & 1;            // 2 warps along M
    const int wn = warpId >> 1;           // 2 warps along N
    const int rw = wm * 64, cw = wn * 64;
    const int gid = lane >> 2;            // groupID 0..7
    const int tig = lane & 3;             // thread-in-group 0..3

    const int bm = blockIdx.y, bn = blockIdx.x;
    const float* Ab = gi.A + (size_t)bm * BMG * C_;
    const float* Wb = gi.W + (size_t)bn * BNG * C_;

    const uint32_t smb = smem_u32(smg);
    const uint32_t* smU = reinterpret_cast<const uint32_t*>(smg);

    auto load_stage = [&](int s, int kt) {
        uint32_t sb = smb + s * (STF * 4);
        int k0 = kt * BKG;
#pragma unroll
        for (int i = 0; i < 8; i++) {
            int f = tid + i * 128;        // 0..1023
            int row = f >> 3;
            int ch  = f & 7;
            cp_async16(sb + row * (RS * 4) + ch * 16,
                       Ab + (size_t)row * C_ + k0 + ch * 4);
            cp_async16(sb + AST * 4 + row * (RS * 4) + ch * 16,
                       Wb + (size_t)row * C_ + k0 + ch * 4);
        }
        cp_commit();
    };

    float acc[32][4];
#pragma unroll
    for (int i = 0; i < 32; i++)
#pragma unroll
        for (int j = 0; j < 4; j++) acc[i][j] = 0.0f;

    uint32_t af[2][16], bf[2][16];

    load_stage(0, 0);
    load_stage(1, 1);

    for (int kt = 0; kt < NKT; kt++) {
        const int s = kt & 1;
        if (kt + 1 < NKT) cp_wait<1>(); else cp_wait<0>();
        __syncthreads();

        const int sbase = s * STF;
        const int aoff = sbase + (rw + gid) * RS + tig;
        const int boff = sbase + AST + (cw + gid) * RS + tig;

        auto ldA = [&](int buf, int kk) {
#pragma unroll
            for (int mt = 0; mt < 4; mt++) {
                int base = aoff + mt * (16 * RS) + kk * 8;
                af[buf][mt*4+0] = smU[base];
                af[buf][mt*4+1] = smU[base + 8 * RS];
                af[buf][mt*4+2] = smU[base + 4];
                af[buf][mt*4+3] = smU[base + 8 * RS + 4];
            }
        };
        auto ldB = [&](int buf, int kk) {
#pragma unroll
            for (int nt = 0; nt < 8; nt++) {
                int base = boff + nt * (8 * RS) + kk * 8;
                bf[buf][nt*2+0] = smU[base];
                bf[buf][nt*2+1] = smU[base + 4];
            }
        };

        ldA(0, 0); ldB(0, 0);
        int pb = 0;
#pragma unroll
        for (int kk = 0; kk < 4; kk++) {
            if (kk < 3) { ldA(pb ^ 1, kk + 1); ldB(pb ^ 1, kk + 1); }
#pragma unroll
            for (int mt = 0; mt < 4; mt++)
#pragma unroll
                for (int nt = 0; nt < 8; nt++)
                    MMA_TF32(acc[mt*8+nt], af[pb] + mt*4, bf[pb] + nt*2);
            pb ^= 1;
        }

        __syncthreads();                 // all warps done reading stage s
        if (kt + 2 < NKT) load_stage(s, kt + 2);
    }

    // Epilogue (light only)
    const int act = gi.act;
    float* O = gi.O;
#pragma unroll
    for (int mt = 0; mt < 4; mt++) {
        int r0 = bm * BMG + rw + mt * 16 + gid;
#pragma unroll
        for (int nt = 0; nt < 8; nt++) {
            int col = bn * BNG + cw + nt * 8 + tig * 2;
            float v0 = acc[mt*8+nt][0], v1 = acc[mt*8+nt][1];
            float v2 = acc[mt*8+nt][2], v3 = acc[mt*8+nt][3];
            if (act == 1) {
                v0 = rtf(tanhf(v0)); v1 = rtf(tanhf(v1));
                v2 = rtf(tanhf(v2)); v3 = rtf(tanhf(v3));
            } else if (act == 2) {
                v0 = rtf(sigm(v0)); v1 = rtf(sigm(v1));
                v2 = rtf(sigm(v2)); v3 = rtf(sigm(v3));
            } else if (act == 3) {
                v0 = rtf(v0); v1 = rtf(v1); v2 = rtf(v2); v3 = rtf(v3);
            }
            *reinterpret_cast<float2*>(O + (size_t)r0 * C_ + col) = make_float2(v0, v1);
            *reinterpret_cast<float2*>(O + (size_t)(r0 + 8) * C_ + col) = make_float2(v2, v3);
        }
    }
}

// ---------------------------------------------------------------------------
// K5: stage-2 fused elementwise (w decay / k adjust / v blend), in place
// ---------------------------------------------------------------------------
__global__ __launch_bounds__(256) void ew2_kernel(
    float* __restrict__ w2, const float* __restrict__ a2, const float* __restrict__ v2,
    float* __restrict__ k, float* __restrict__ v, const float* __restrict__ v_first,
    const float* __restrict__ w0, const float* __restrict__ a0,
    const float* __restrict__ v0, const float* __restrict__ k_a)
{
    const int NC4 = C_ / 4;
    int e4 = blockIdx.x * 256 + threadIdx.x;
    if (e4 >= (int)(SLOT / 4)) return;
    int c4 = e4 % NC4;

    float4 w0v = reinterpret_cast<const float4*>(w0)[c4];
    float4 a0v = reinterpret_cast<const float4*>(a0)[c4];
    float4 v0v = reinterpret_cast<const float4*>(v0)[c4];
    float4 kav = reinterpret_cast<const float4*>(k_a)[c4];

    float4* W2v = reinterpret_cast<float4*>(w2);
    float4* Kv  = reinterpret_cast<float4*>(k);
    float4* Vv  = reinterpret_cast<float4*>(v);
    const float4* A2v = reinterpret_cast<const float4*>(a2);
    const float4* V2v = reinterpret_cast<const float4*>(v2);
    const float4* VFv = reinterpret_cast<const float4*>(v_first);

    float4 wr = W2v[e4];
    wr.x = expf(-0.606531f * sigm(w0v.x + wr.x));
    wr.y = expf(-0.606531f * sigm(w0v.y + wr.y));
    wr.z = expf(-0.606531f * sigm(w0v.z + wr.z));
    wr.w = expf(-0.606531f * sigm(w0v.w + wr.w));
    W2v[e4] = wr;

    float4 ar = A2v[e4];
    float ax = sigm(a0v.x + ar.x), ay = sigm(a0v.y + ar.y);
    float az = sigm(a0v.z + ar.z), aw = sigm(a0v.w + ar.w);
    float4 kv = Kv[e4];
    kv.x *= 1.0f + (ax - 1.0f) * kav.x;
    kv.y *= 1.0f + (ay - 1.0f) * kav.y;
    kv.z *= 1.0f + (az - 1.0f) * kav.z;
    kv.w *= 1.0f + (aw - 1.0f) * kav.w;
    Kv[e4] = kv;

    float4 vr = V2v[e4];
    float sx = sigm(v0v.x + vr.x), sy = sigm(v0v.y + vr.y);
    float sz = sigm(v0v.z + vr.z), sw = sigm(v0v.w + vr.w);
    float4 vv = Vv[e4];
    float4 vf = VFv[e4];
    vv.x += (vf.x - vv.x) * sx;
    vv.y += (vf.y - vv.y) * sy;
    vv.z += (vf.z - vv.z) * sz;
    vv.w += (vf.w - vv.w) * sw;
    Vv[e4] = vv;
}

// ---------------------------------------------------------------------------
// K6: WKV-7 scan — smem-chunked monolithic (R6-proven, fastest measured).
// 128 blocks x 128 threads; cp.async double-buffered chunks of 8 timesteps.
// ---------------------------------------------------------------------------
#define WCH 8                     // timesteps per chunk
#define NCHUNK (T_ / WCH)         // 256
#define RB_OFF 0
#define VB_OFF 1024
#define WB_OFF 2048
#define KB_OFF 2304
#define WKV_SMEM_FLOATS 2560

__global__ __launch_bounds__(128) void wkv_kernel(
    const float* __restrict__ R, const float* __restrict__ Wd,
    const float* __restrict__ K, const float* __restrict__ V, float* __restrict__ Y)
{
    __shared__ float sm[WKV_SMEM_FLOATS];

    const int bh = blockIdx.x >> 2;        // 0..31
    const int rg = blockIdx.x & 3;         // 16-row group
    const int b  = bh >> 4;
    const int h  = bh & 15;
    const int tid = threadIdx.x;
    const int il  = tid >> 3;              // local row 0..15
    const int jq  = tid & 7;               // j-slice (8 cols)
    const int i   = rg * 16 + il;          // head-local row
    const size_t base = ((size_t)b * T_) * C_ + (size_t)h * NH;

    const uint32_t smb = smem_u32(sm);

    auto load_chunk = [&](int buf, int c) {
        int t0 = c * WCH;
        int s   = tid >> 4;
        int seg = tid & 15;
        const float* rs = R + base + (size_t)(t0 + s) * C_ + seg * 4;
        const float* vs = V + base + (size_t)(t0 + s) * C_ + seg * 4;
        cp_async16(smb + (RB_OFF + buf * 512 + s * 64 + seg * 4) * 4, rs);
        cp_async16(smb + (VB_OFF + buf * 512 + s * 64 + seg * 4) * 4, vs);
        if (tid < 32) {
            int s2 = tid >> 2, seg2 = tid & 3;
            cp_async16(smb + (WB_OFF + buf * 128 + s2 * 16 + seg2 * 4) * 4,
                       Wd + base + (size_t)(t0 + s2) * C_ + rg * 16 + seg2 * 4);
        } else if (tid < 64) {
            int t2 = tid - 32;
            int s2 = t2 >> 2, seg2 = t2 & 3;
            cp_async16(smb + (KB_OFF + buf * 128 + s2 * 16 + seg2 * 4) * 4,
                       K + base + (size_t)(t0 + s2) * C_ + rg * 16 + seg2 * 4);
        }
        cp_commit();
    };

    float S[8];
#pragma unroll
    for (int u = 0; u < 8; u++) S[u] = 0.0f;

    load_chunk(0, 0);
    load_chunk(1, 1);

    for (int c = 0; c < NCHUNK; c++) {
        const int buf = c & 1;
        if (c + 1 < NCHUNK) cp_wait<1>(); else cp_wait<0>();
        __syncthreads();

        const float* rb = sm + RB_OFF + buf * 512;
        const float* vb = sm + VB_OFF + buf * 512;
        const float* wb = sm + WB_OFF + buf * 128;
        const float* kb = sm + KB_OFF + buf * 128;

#pragma unroll
        for (int s = 0; s < WCH; s++) {
            float4 r0 = *reinterpret_cast<const float4*>(rb + s * 64 + jq * 8);
            float4 r1 = *reinterpret_cast<const float4*>(rb + s * 64 + jq * 8 + 4);
            float4 v0 = *reinterpret_cast<const float4*>(vb + s * 64 + jq * 8);
            float4 v1 = *reinterpret_cast<const float4*>(vb + s * 64 + jq * 8 + 4);
            const float wi = wb[s * 16 + il];
            const float ki = kb[s * 16 + il];

            float a0 = 0.f, a1 = 0.f;
            float t0v = S[0] * wi + ki * v0.x; S[0] = t0v; a0 += t0v * r0.x;
            float t1v = S[1] * wi + ki * v0.y; S[1] = t1v; a1 += t1v * r0.y;
            float t2v = S[2] * wi + ki * v0.z; S[2] = t2v; a0 += t2v * r0.z;
            float t3v = S[3] * wi + ki * v0.w; S[3] = t3v; a1 += t3v * r0.w;
            float t4v = S[4] * wi + ki * v1.x; S[4] = t4v; a0 += t4v * r1.x;
            float t5v = S[5] * wi + ki * v1.y; S[5] = t5v; a1 += t5v * r1.y;
            float t6v = S[6] * wi + ki * v1.z; S[6] = t6v; a0 += t6v * r1.z;
            float t7v = S[7] * wi + ki * v1.w; S[7] = t7v; a1 += t7v * r1.w;

            float red = a0 + a1;
            red += __shfl_xor_sync(0xffffffffu, red, 1);
            red += __shfl_xor_sync(0xffffffffu, red, 2);
            red += __shfl_xor_sync(0xffffffffu, red, 4);
            if (jq == 0) Y[base + (size_t)(c * WCH + s) * C_ + i] = red;
        }

        __syncthreads();
        if (c + 2 < NCHUNK) load_chunk(buf, c + 2);
        else cp_commit();
    }
}

// ---------------------------------------------------------------------------
// K7: LayerNorm(C) + rkv residual + gate:  z = (LN(y) + rkv) * g   (tf32 out)
// ---------------------------------------------------------------------------
__global__ __launch_bounds__(256) void ln_gate_kernel(
    const float* __restrict__ Yb, const float* __restrict__ Rb, const float* __restrict__ Kb,
    const float* __restrict__ Vb, const float* __restrict__ Gb,
    const float* __restrict__ rk, const float* __restrict__ lng, const float* __restrict__ lnb,
    float* __restrict__ Zb)
{
    const int m = blockIdx.x;
    const size_t base = (size_t)m * C_;
    __shared__ float sprod[C_];
    __shared__ float hdot[H_];
    __shared__ float rs[8], rq[8], stats[2];

    const int tid = threadIdx.x;
    float yv[4];
    float lsum = 0.f, lsq = 0.f;
#pragma unroll
    for (int u = 0; u < 4; u++) {
        int c = tid + u * 256;
        float t = Yb[base + c];
        yv[u] = t; lsum += t; lsq += t * t;
        sprod[c] = Rb[base + c] * Kb[base + c] * rk[c];
    }
#pragma unroll
    for (int o = 16; o > 0; o >>= 1) {
        lsum += __shfl_xor_sync(0xffffffffu, lsum, o);
        lsq  += __shfl_xor_sync(0xffffffffu, lsq,  o);
    }
    if ((tid & 31) == 0) { rs[tid >> 5] = lsum; rq[tid >> 5] = lsq; }
    __syncthreads();
    if (tid == 0) {
        float sv = 0.f, qv = 0.f;
        for (int wq = 0; wq < 8; wq++) { sv += rs[wq]; qv += rq[wq]; }
        float mu = sv / (float)C_;
        stats[0] = mu;
        stats[1] = rsqrtf(qv / (float)C_ - mu * mu + 1e-5f);
    }
    if (tid < 16) {
        float d = 0.f;
        for (int n = 0; n < 64; n++) d += sprod[tid * 64 + n];
        hdot[tid] = d;
    }
    __syncthreads();
    const float mu = stats[0], rstd = stats[1];
#pragma unroll
    for (int u = 0; u < 4; u++) {
        int c = tid + u * 256;
        int hh = c >> 6;
        float z = ((yv[u] - mu) * rstd * lng[c] + lnb[c] + hdot[hh] * Vb[base + c]) * Gb[base + c];
        Zb[base + c] = rtf(z);
    }
}

// ---------------------------------------------------------------------------
// Launcher
// ---------------------------------------------------------------------------
extern "C" void kernel_launch(void* const* d_in, const int* in_sizes, int n_in,
                              void* d_out, int out_size)
{
    (void)in_sizes; (void)n_in; (void)out_size;
    const float* x       = (const float*)d_in[0];
    const float* v_first = (const float*)d_in[1];
    const float* Wr  = (const float*)d_in[2];
    const float* Wk  = (const float*)d_in[3];
    const float* Wv  = (const float*)d_in[4];
    const float* Wo  = (const float*)d_in[5];
    const float* Wg1 = (const float*)d_in[6];
    const float* Wg2 = (const float*)d_in[7];
    const float* W1  = (const float*)d_in[8];
    const float* W2  = (const float*)d_in[9];
    const float* A1  = (const float*)d_in[10];
    const float* A2  = (const float*)d_in[11];
    const float* V1  = (const float*)d_in[12];
    const float* V2  = (const float*)d_in[13];
    const float* tm_r = (const float*)d_in[14];
    const float* tm_w = (const float*)d_in[15];
    const float* tm_k = (const float*)d_in[16];
    const float* tm_v = (const float*)d_in[17];
    const float* tm_a = (const float*)d_in[18];
    const float* tm_g = (const float*)d_in[19];
    const float* w0  = (const float*)d_in[20];
    const float* a0  = (const float*)d_in[21];
    const float* v0  = (const float*)d_in[22];
    const float* k_a = (const float*)d_in[24];
    const float* r_k = (const float*)d_in[25];
    const float* ln_g = (const float*)d_in[26];
    const float* ln_b = (const float*)d_in[27];

    float* buf = nullptr;
    cudaGetSymbolAddress((void**)&buf, g_scratch);
    auto S  = [&](int s) { return buf + (size_t)s * SLOT; };
    float* wbase = buf + 19 * SLOT;
    auto WB = [&](int w) { return (const float*)(wbase + (size_t)w * WSLOT); };

    cudaFuncSetAttribute((const void*)gemm_mma_kernel,
                         cudaFuncAttributeMaxDynamicSharedMemorySize, GEMM_SMEM);

    const int EW_BLOCKS = MROWS * C_ / 4 / 256;   // 4096
    dim3 gg(C_ / BNG, MROWS / BMG);               // (8, 32)

    // K0: tf32-round the weights
    Ptr12 ws;
    ws.p[0] = Wr;  ws.p[1] = Wk;  ws.p[2] = Wv;  ws.p[3] = W1;
    ws.p[4] = A1;  ws.p[5] = V1;  ws.p[6] = Wg1; ws.p[7] = W2;
    ws.p[8] = A2;  ws.p[9] = V2;  ws.p[10] = Wg2; ws.p[11] = Wo;
    wcvt_kernel<<<dim3(1024, 12), 256>>>(ws, wbase);

    // K1: token-shift mixes -> slots 0..5, tf32-rounded
    mix_kernel<<<EW_BLOCKS, 256>>>(x, tm_r, tm_w, tm_k, tm_v, tm_a, tm_g, buf);

    // Stage-1 batched GEMMs (7)
    GemmBatch7 b1;
    b1.it[0] = { S(0), WB(0), S(6),  0 };   // r
    b1.it[1] = { S(2), WB(1), S(7),  0 };   // k
    b1.it[2] = { S(3), WB(2), S(8),  0 };   // v
    b1.it[3] = { S(1), WB(3), S(9),  1 };   // w1 = tanh(.)
    b1.it[4] = { S(4), WB(4), S(10), 3 };   // a1
    b1.it[5] = { S(3), WB(5), S(11), 3 };   // v1
    b1.it[6] = { S(5), WB(6), S(12), 2 };   // g1 = sigmoid(.)
    gemm_mma_kernel<<<dim3(gg.x, gg.y, 7), 128, GEMM_SMEM>>>(b1);

    // Stage-2 batched GEMMs (4), plain outputs
    GemmBatch7 b2;
    b2.it[0] = { S(9),  WB(7),  S(13), 0 };
    b2.it[1] = { S(10), WB(8),  S(14), 0 };
    b2.it[2] = { S(11), WB(9),  S(15), 0 };
    b2.it[3] = { S(12), WB(10), S(16), 0 };
    gemm_mma_kernel<<<dim3(gg.x, gg.y, 4), 128, GEMM_SMEM>>>(b2);

    // K5: w decay, k adjust, v blend
    ew2_kernel<<<EW_BLOCKS, 256>>>(S(13), S(14), S(15), S(7), S(8), v_first,
                                   w0, a0, v0, k_a);

    // K6: WKV scan -> y
    wkv_kernel<<<128, 128>>>(S(6), S(13), S(7), S(8), S(17));

    // K7: LN + rkv + gate -> z, tf32-rounded
    ln_gate_kernel<<<MROWS, 256>>>(S(17), S(6), S(7), S(8), S(16),
                                   r_k, ln_g, ln_b, S(18));

    // Final GEMM: out = z @ Wo^T
    GemmBatch7 b3;
    b3.it[0] = { S(18), WB(11), (float*)d_out, 0 };
    gemm_mma_kernel<<<dim3(gg.x, gg.y, 1), 128, GEMM_SMEM>>>(b3);
}

// round 17
// speedup vs baseline: 1.1374x; 1.0232x over previous
#include <cuda_runtime.h>
#include <cuda_bf16.h>
#include <cstdint>
#include <cstddef>

// Problem dims
#define B_    2
#define T_    2048
#define C_    1024
#define H_    16
#define NH    64
#define MROWS 4096                       // B*T
constexpr size_t SLOT = (size_t)MROWS * C_;   // 4,194,304 elements per scratch slot
constexpr size_t WSLOT = (size_t)C_ * C_;     // 1,048,576 elements per weight

// Scratch slots:
// 0:xr 1:xw 2:xk 3:xv 4:xa 5:xg
// 6:r 7:k 8:v 9:w1(tanh'd) 10:a1 11:v1 12:g1(sigmoid'd)
// 13:w2raw(->w) 14:a2raw 15:v2raw 16:g 17:y 18:z
// then 12 tf32-rounded weight copies
__device__ float g_scratch[19ull * 4194304ull + 12ull * 1048576ull];

__device__ __forceinline__ float sigm(float x) { return 1.0f / (1.0f + expf(-x)); }
__device__ __forceinline__ float rtf(float x) {
    float r; asm("cvt.rna.tf32.f32 %0, %1;" : "=f"(r) : "f"(x)); return r;
}
__device__ __forceinline__ float4 rtf4(float4 v) {
    return make_float4(rtf(v.x), rtf(v.y), rtf(v.z), rtf(v.w));
}

__device__ __forceinline__ uint32_t smem_u32(const void* p) {
    uint32_t a;
    asm("{ .reg .u64 t; cvta.to.shared.u64 t, %1; cvt.u32.u64 %0, t; }" : "=r"(a) : "l"(p));
    return a;
}
__device__ __forceinline__ void cp_async16(uint32_t s, const void* g) {
    asm volatile("cp.async.ca.shared.global [%0], [%1], 16;\n" :: "r"(s), "l"(g));
}
__device__ __forceinline__ void cp_commit() { asm volatile("cp.async.commit_group;\n"); }
template <int Nn> __device__ __forceinline__ void cp_wait() {
    asm volatile("cp.async.wait_group %0;\n" :: "n"(Nn));
}

// ---------------------------------------------------------------------------
// K1: fused (token-shift mixing + tf32 weight rounding) in ONE launch.
// blocks [0, 4096)             -> mix: 6 tf32-rounded shift-mixes of x
// blocks [4096, 4096+3072)     -> weight convert (12 x 1Mi elements)
// ---------------------------------------------------------------------------
struct Ptr12 { const float* p[12]; };

#define MIX_BLOCKS 4096
#define WCV_BLOCKS 3072

__global__ __launch_bounds__(256) void mix_wcvt_kernel(
    const float* __restrict__ X,
    const float* __restrict__ tmr, const float* __restrict__ tmw,
    const float* __restrict__ tmk, const float* __restrict__ tmv,
    const float* __restrict__ tma, const float* __restrict__ tmg,
    Ptr12 ws, float* __restrict__ buf, float* __restrict__ wout)
{
    const int bx = blockIdx.x;
    if (bx < MIX_BLOCKS) {
        const int NC4 = C_ / 4;
        int e4 = bx * 256 + threadIdx.x;
        int m  = e4 / NC4;
        int c4 = e4 - m * NC4;
        int t  = m & (T_ - 1);

        const float4* X4 = reinterpret_cast<const float4*>(X);
        float4 xc = X4[e4];
        float4 xp = make_float4(0.f, 0.f, 0.f, 0.f);
        if (t != 0) xp = X4[e4 - NC4];
        float4 xx = make_float4(xp.x - xc.x, xp.y - xc.y, xp.z - xc.z, xp.w - xc.w);

        float4* out = reinterpret_cast<float4*>(buf);
        const float* tms[6] = {tmr, tmw, tmk, tmv, tma, tmg};
#pragma unroll
        for (int s = 0; s < 6; s++) {
            float4 tm = reinterpret_cast<const float4*>(tms[s])[c4];
            float4 o = make_float4(xc.x + xx.x * tm.x, xc.y + xx.y * tm.y,
                                   xc.z + xx.z * tm.z, xc.w + xx.w * tm.w);
            out[(size_t)s * (SLOT / 4) + e4] = rtf4(o);
        }
    } else {
        // weight convert: 12 * 262144 float4 = 3,145,728 float4 total
        const int wb = bx - MIX_BLOCKS;                  // 0..3071
        int idx4 = wb * 256 + threadIdx.x;               // stride 786432, 4 iters
#pragma unroll
        for (int it = 0; it < 4; it++) {
            int w  = idx4 >> 18;                         // / 262144
            int e4 = idx4 & 262143;
            float4 v = reinterpret_cast<const float4*>(ws.p[w])[e4];
            reinterpret_cast<float4*>(wout + (size_t)w * WSLOT)[e4] = rtf4(v);
            idx4 += WCV_BLOCKS * 256;
        }
    }
}

// ---------------------------------------------------------------------------
// K2: hand-rolled TF32 mma GEMM (R5-measured-best config: BK=32, 2-stage,
// 4 warps 2Mx2N, warp tile 64x64, register double-buffered fragments,
// LIGHT epilogues only).  out[m,n] = sum_k A[m,k] * W[n,k]
// Epilogue act: 0 none, 1 tanh+round, 2 sigmoid+round, 3 round.
// ---------------------------------------------------------------------------
#define BMG 128
#define BNG 128
#define BKG 32
#define NKT (C_ / BKG)        // 32
#define RS  36                // padded row stride in floats (32 + 4)
#define AST (128 * RS)        // floats per matrix tile per stage (4608)
#define STF (2 * AST)         // floats per stage (9216)
constexpr int GEMM_SMEM = 2 * STF * 4;   // 73728 bytes

struct GemmItem { const float* A; const float* W; float* O; int act; };
struct GemmBatch7 { GemmItem it[7]; };

#define MMA_TF32(d, a, b) \
    asm volatile( \
        "mma.sync.aligned.m16n8k8.row.col.f32.tf32.tf32.f32 " \
        "{%0,%1,%2,%3}, {%4,%5,%6,%7}, {%8,%9}, {%0,%1,%2,%3};" \
        : "+f"((d)[0]), "+f"((d)[1]), "+f"((d)[2]), "+f"((d)[3]) \
        : "r"((a)[0]), "r"((a)[1]), "r"((a)[2]), "r"((a)[3]), \
          "r"((b)[0]), "r"((b)[1]))

extern __shared__ float smg[];

__global__ __launch_bounds__(128, 2) void gemm_mma_kernel(GemmBatch7 bt)
{
    const GemmItem gi = bt.it[blockIdx.z];
    const int tid  = threadIdx.x;
    const int lane = tid & 31;
    const int warpId = tid >> 5;
    const int wm = warpId & 1;            // 2 warps along M
    const int wn = warpId >> 1;           // 2 warps along N
    const int rw = wm * 64, cw = wn * 64;
    const int gid = lane >> 2;            // groupID 0..7
    const int tig = lane & 3;             // thread-in-group 0..3

    const int bm = blockIdx.y, bn = blockIdx.x;
    const float* Ab = gi.A + (size_t)bm * BMG * C_;
    const float* Wb = gi.W + (size_t)bn * BNG * C_;

    const uint32_t smb = smem_u32(smg);
    const uint32_t* smU = reinterpret_cast<const uint32_t*>(smg);

    auto load_stage = [&](int s, int kt) {
        uint32_t sb = smb + s * (STF * 4);
        int k0 = kt * BKG;
#pragma unroll
        for (int i = 0; i < 8; i++) {
            int f = tid + i * 128;        // 0..1023
            int row = f >> 3;
            int ch  = f & 7;
            cp_async16(sb + row * (RS * 4) + ch * 16,
                       Ab + (size_t)row * C_ + k0 + ch * 4);
            cp_async16(sb + AST * 4 + row * (RS * 4) + ch * 16,
                       Wb + (size_t)row * C_ + k0 + ch * 4);
        }
        cp_commit();
    };

    float acc[32][4];
#pragma unroll
    for (int i = 0; i < 32; i++)
#pragma unroll
        for (int j = 0; j < 4; j++) acc[i][j] = 0.0f;

    uint32_t af[2][16], bf[2][16];

    load_stage(0, 0);
    load_stage(1, 1);

    for (int kt = 0; kt < NKT; kt++) {
        const int s = kt & 1;
        if (kt + 1 < NKT) cp_wait<1>(); else cp_wait<0>();
        __syncthreads();

        const int sbase = s * STF;
        const int aoff = sbase + (rw + gid) * RS + tig;
        const int boff = sbase + AST + (cw + gid) * RS + tig;

        auto ldA = [&](int buf, int kk) {
#pragma unroll
            for (int mt = 0; mt < 4; mt++) {
                int base = aoff + mt * (16 * RS) + kk * 8;
                af[buf][mt*4+0] = smU[base];
                af[buf][mt*4+1] = smU[base + 8 * RS];
                af[buf][mt*4+2] = smU[base + 4];
                af[buf][mt*4+3] = smU[base + 8 * RS + 4];
            }
        };
        auto ldB = [&](int buf, int kk) {
#pragma unroll
            for (int nt = 0; nt < 8; nt++) {
                int base = boff + nt * (8 * RS) + kk * 8;
                bf[buf][nt*2+0] = smU[base];
                bf[buf][nt*2+1] = smU[base + 4];
            }
        };

        ldA(0, 0); ldB(0, 0);
        int pb = 0;
#pragma unroll
        for (int kk = 0; kk < 4; kk++) {
            if (kk < 3) { ldA(pb ^ 1, kk + 1); ldB(pb ^ 1, kk + 1); }
#pragma unroll
            for (int mt = 0; mt < 4; mt++)
#pragma unroll
                for (int nt = 0; nt < 8; nt++)
                    MMA_TF32(acc[mt*8+nt], af[pb] + mt*4, bf[pb] + nt*2);
            pb ^= 1;
        }

        __syncthreads();                 // all warps done reading stage s
        if (kt + 2 < NKT) load_stage(s, kt + 2);
    }

    // Epilogue (light only)
    const int act = gi.act;
    float* O = gi.O;
#pragma unroll
    for (int mt = 0; mt < 4; mt++) {
        int r0 = bm * BMG + rw + mt * 16 + gid;
#pragma unroll
        for (int nt = 0; nt < 8; nt++) {
            int col = bn * BNG + cw + nt * 8 + tig * 2;
            float v0 = acc[mt*8+nt][0], v1 = acc[mt*8+nt][1];
            float v2 = acc[mt*8+nt][2], v3 = acc[mt*8+nt][3];
            if (act == 1) {
                v0 = rtf(tanhf(v0)); v1 = rtf(tanhf(v1));
                v2 = rtf(tanhf(v2)); v3 = rtf(tanhf(v3));
            } else if (act == 2) {
                v0 = rtf(sigm(v0)); v1 = rtf(sigm(v1));
                v2 = rtf(sigm(v2)); v3 = rtf(sigm(v3));
            } else if (act == 3) {
                v0 = rtf(v0); v1 = rtf(v1); v2 = rtf(v2); v3 = rtf(v3);
            }
            *reinterpret_cast<float2*>(O + (size_t)r0 * C_ + col) = make_float2(v0, v1);
            *reinterpret_cast<float2*>(O + (size_t)(r0 + 8) * C_ + col) = make_float2(v2, v3);
        }
    }
}

// ---------------------------------------------------------------------------
// K5: stage-2 fused elementwise (w decay / k adjust / v blend), in place
// ---------------------------------------------------------------------------
__global__ __launch_bounds__(256) void ew2_kernel(
    float* __restrict__ w2, const float* __restrict__ a2, const float* __restrict__ v2,
    float* __restrict__ k, float* __restrict__ v, const float* __restrict__ v_first,
    const float* __restrict__ w0, const float* __restrict__ a0,
    const float* __restrict__ v0, const float* __restrict__ k_a)
{
    const int NC4 = C_ / 4;
    int e4 = blockIdx.x * 256 + threadIdx.x;
    if (e4 >= (int)(SLOT / 4)) return;
    int c4 = e4 % NC4;

    float4 w0v = reinterpret_cast<const float4*>(w0)[c4];
    float4 a0v = reinterpret_cast<const float4*>(a0)[c4];
    float4 v0v = reinterpret_cast<const float4*>(v0)[c4];
    float4 kav = reinterpret_cast<const float4*>(k_a)[c4];

    float4* W2v = reinterpret_cast<float4*>(w2);
    float4* Kv  = reinterpret_cast<float4*>(k);
    float4* Vv  = reinterpret_cast<float4*>(v);
    const float4* A2v = reinterpret_cast<const float4*>(a2);
    const float4* V2v = reinterpret_cast<const float4*>(v2);
    const float4* VFv = reinterpret_cast<const float4*>(v_first);

    float4 wr = W2v[e4];
    wr.x = expf(-0.606531f * sigm(w0v.x + wr.x));
    wr.y = expf(-0.606531f * sigm(w0v.y + wr.y));
    wr.z = expf(-0.606531f * sigm(w0v.z + wr.z));
    wr.w = expf(-0.606531f * sigm(w0v.w + wr.w));
    W2v[e4] = wr;

    float4 ar = A2v[e4];
    float ax = sigm(a0v.x + ar.x), ay = sigm(a0v.y + ar.y);
    float az = sigm(a0v.z + ar.z), aw = sigm(a0v.w + ar.w);
    float4 kv = Kv[e4];
    kv.x *= 1.0f + (ax - 1.0f) * kav.x;
    kv.y *= 1.0f + (ay - 1.0f) * kav.y;
    kv.z *= 1.0f + (az - 1.0f) * kav.z;
    kv.w *= 1.0f + (aw - 1.0f) * kav.w;
    Kv[e4] = kv;

    float4 vr = V2v[e4];
    float sx = sigm(v0v.x + vr.x), sy = sigm(v0v.y + vr.y);
    float sz = sigm(v0v.z + vr.z), sw = sigm(v0v.w + vr.w);
    float4 vv = Vv[e4];
    float4 vf = VFv[e4];
    vv.x += (vf.x - vv.x) * sx;
    vv.y += (vf.y - vv.y) * sy;
    vv.z += (vf.z - vv.z) * sz;
    vv.w += (vf.w - vv.w) * sw;
    Vv[e4] = vv;
}

// ---------------------------------------------------------------------------
// K6: WKV-7 scan — smem-chunked monolithic, WCH=16 (half the barriers of R6).
// 128 blocks x 128 threads; cp.async double-buffered chunks of 16 timesteps.
// ---------------------------------------------------------------------------
#define WCH 16                    // timesteps per chunk
#define NCHUNK (T_ / WCH)         // 128
#define RB_OFF 0                  // r: 2 bufs x 16 steps x 64 = 2048
#define VB_OFF 2048
#define WB_OFF 4096               // w: 2 bufs x 16 steps x 16 = 512
#define KB_OFF 4608
#define WKV_SMEM_FLOATS 5120

__global__ __launch_bounds__(128) void wkv_kernel(
    const float* __restrict__ R, const float* __restrict__ Wd,
    const float* __restrict__ K, const float* __restrict__ V, float* __restrict__ Y)
{
    __shared__ float sm[WKV_SMEM_FLOATS];

    const int bh = blockIdx.x >> 2;        // 0..31
    const int rg = blockIdx.x & 3;         // 16-row group
    const int b  = bh >> 4;
    const int h  = bh & 15;
    const int tid = threadIdx.x;
    const int il  = tid >> 3;              // local row 0..15
    const int jq  = tid & 7;               // j-slice (8 cols)
    const int i   = rg * 16 + il;          // head-local row
    const size_t base = ((size_t)b * T_) * C_ + (size_t)h * NH;

    const uint32_t smb = smem_u32(sm);

    auto load_chunk = [&](int buf, int c) {
        int t0 = c * WCH;
        // r, v: 16 steps x 64 floats = 256 float4 each -> 2 per thread
        int s   = tid >> 4;                // step 0..7 (+8 on 2nd iter)
        int seg = tid & 15;
#pragma unroll
        for (int q = 0; q < 2; q++) {
            int st = s + q * 8;
            const float* rs = R + base + (size_t)(t0 + st) * C_ + seg * 4;
            const float* vs = V + base + (size_t)(t0 + st) * C_ + seg * 4;
            cp_async16(smb + (RB_OFF + buf * 1024 + st * 64 + seg * 4) * 4, rs);
            cp_async16(smb + (VB_OFF + buf * 1024 + st * 64 + seg * 4) * 4, vs);
        }
        // w: threads 0..63, k: threads 64..127 (16 steps x 16 floats = 64 x 16B)
        if (tid < 64) {
            int s2 = tid >> 2, sg = tid & 3;
            cp_async16(smb + (WB_OFF + buf * 256 + s2 * 16 + sg * 4) * 4,
                       Wd + base + (size_t)(t0 + s2) * C_ + rg * 16 + sg * 4);
        } else {
            int t2 = tid - 64;
            int s2 = t2 >> 2, sg = t2 & 3;
            cp_async16(smb + (KB_OFF + buf * 256 + s2 * 16 + sg * 4) * 4,
                       K + base + (size_t)(t0 + s2) * C_ + rg * 16 + sg * 4);
        }
        cp_commit();
    };

    float S[8];
#pragma unroll
    for (int u = 0; u < 8; u++) S[u] = 0.0f;

    load_chunk(0, 0);
    load_chunk(1, 1);

    for (int c = 0; c < NCHUNK; c++) {
        const int buf = c & 1;
        if (c + 1 < NCHUNK) cp_wait<1>(); else cp_wait<0>();
        __syncthreads();

        const float* rb = sm + RB_OFF + buf * 1024;
        const float* vb = sm + VB_OFF + buf * 1024;
        const float* wb = sm + WB_OFF + buf * 256;
        const float* kb = sm + KB_OFF + buf * 256;

#pragma unroll
        for (int s = 0; s < WCH; s++) {
            float4 r0 = *reinterpret_cast<const float4*>(rb + s * 64 + jq * 8);
            float4 r1 = *reinterpret_cast<const float4*>(rb + s * 64 + jq * 8 + 4);
            float4 v0 = *reinterpret_cast<const float4*>(vb + s * 64 + jq * 8);
            float4 v1 = *reinterpret_cast<const float4*>(vb + s * 64 + jq * 8 + 4);
            const float wi = wb[s * 16 + il];
            const float ki = kb[s * 16 + il];

            float a0 = 0.f, a1 = 0.f;
            float t0v = S[0] * wi + ki * v0.x; S[0] = t0v; a0 += t0v * r0.x;
            float t1v = S[1] * wi + ki * v0.y; S[1] = t1v; a1 += t1v * r0.y;
            float t2v = S[2] * wi + ki * v0.z; S[2] = t2v; a0 += t2v * r0.z;
            float t3v = S[3] * wi + ki * v0.w; S[3] = t3v; a1 += t3v * r0.w;
            float t4v = S[4] * wi + ki * v1.x; S[4] = t4v; a0 += t4v * r1.x;
            float t5v = S[5] * wi + ki * v1.y; S[5] = t5v; a1 += t5v * r1.y;
            float t6v = S[6] * wi + ki * v1.z; S[6] = t6v; a0 += t6v * r1.z;
            float t7v = S[7] * wi + ki * v1.w; S[7] = t7v; a1 += t7v * r1.w;

            float red = a0 + a1;
            red += __shfl_xor_sync(0xffffffffu, red, 1);
            red += __shfl_xor_sync(0xffffffffu, red, 2);
            red += __shfl_xor_sync(0xffffffffu, red, 4);
            if (jq == 0) Y[base + (size_t)(c * WCH + s) * C_ + i] = red;
        }

        __syncthreads();
        if (c + 2 < NCHUNK) load_chunk(buf, c + 2);
        else cp_commit();
    }
}

// ---------------------------------------------------------------------------
// K7: LayerNorm(C) + rkv residual + gate:  z = (LN(y) + rkv) * g   (tf32 out)
// ---------------------------------------------------------------------------
__global__ __launch_bounds__(256) void ln_gate_kernel(
    const float* __restrict__ Yb, const float* __restrict__ Rb, const float* __restrict__ Kb,
    const float* __restrict__ Vb, const float* __restrict__ Gb,
    const float* __restrict__ rk, const float* __restrict__ lng, const float* __restrict__ lnb,
    float* __restrict__ Zb)
{
    const int m = blockIdx.x;
    const size_t base = (size_t)m * C_;
    __shared__ float sprod[C_];
    __shared__ float hdot[H_];
    __shared__ float rs[8], rq[8], stats[2];

    const int tid = threadIdx.x;
    float yv[4];
    float lsum = 0.f, lsq = 0.f;
#pragma unroll
    for (int u = 0; u < 4; u++) {
        int c = tid + u * 256;
        float t = Yb[base + c];
        yv[u] = t; lsum += t; lsq += t * t;
        sprod[c] = Rb[base + c] * Kb[base + c] * rk[c];
    }
#pragma unroll
    for (int o = 16; o > 0; o >>= 1) {
        lsum += __shfl_xor_sync(0xffffffffu, lsum, o);
        lsq  += __shfl_xor_sync(0xffffffffu, lsq,  o);
    }
    if ((tid & 31) == 0) { rs[tid >> 5] = lsum; rq[tid >> 5] = lsq; }
    __syncthreads();
    if (tid == 0) {
        float sv = 0.f, qv = 0.f;
        for (int wq = 0; wq < 8; wq++) { sv += rs[wq]; qv += rq[wq]; }
        float mu = sv / (float)C_;
        stats[0] = mu;
        stats[1] = rsqrtf(qv / (float)C_ - mu * mu + 1e-5f);
    }
    if (tid < 16) {
        float d = 0.f;
        for (int n = 0; n < 64; n++) d += sprod[tid * 64 + n];
        hdot[tid] = d;
    }
    __syncthreads();
    const float mu = stats[0], rstd = stats[1];
#pragma unroll
    for (int u = 0; u < 4; u++) {
        int c = tid + u * 256;
        int hh = c >> 6;
        float z = ((yv[u] - mu) * rstd * lng[c] + lnb[c] + hdot[hh] * Vb[base + c]) * Gb[base + c];
        Zb[base + c] = rtf(z);
    }
}

// ---------------------------------------------------------------------------
// Launcher — side stream runs the g-GEMM concurrent with b2/ew2/wkv.
// ---------------------------------------------------------------------------
extern "C" void kernel_launch(void* const* d_in, const int* in_sizes, int n_in,
                              void* d_out, int out_size)
{
    (void)in_sizes; (void)n_in; (void)out_size;
    const float* x       = (const float*)d_in[0];
    const float* v_first = (const float*)d_in[1];
    const float* Wr  = (const float*)d_in[2];
    const float* Wk  = (const float*)d_in[3];
    const float* Wv  = (const float*)d_in[4];
    const float* Wo  = (const float*)d_in[5];
    const float* Wg1 = (const float*)d_in[6];
    const float* Wg2 = (const float*)d_in[7];
    const float* W1  = (const float*)d_in[8];
    const float* W2  = (const float*)d_in[9];
    const float* A1  = (const float*)d_in[10];
    const float* A2  = (const float*)d_in[11];
    const float* V1  = (const float*)d_in[12];
    const float* V2  = (const float*)d_in[13];
    const float* tm_r = (const float*)d_in[14];
    const float* tm_w = (const float*)d_in[15];
    const float* tm_k = (const float*)d_in[16];
    const float* tm_v = (const float*)d_in[17];
    const float* tm_a = (const float*)d_in[18];
    const float* tm_g = (const float*)d_in[19];
    const float* w0  = (const float*)d_in[20];
    const float* a0  = (const float*)d_in[21];
    const float* v0  = (const float*)d_in[22];
    const float* k_a = (const float*)d_in[24];
    const float* r_k = (const float*)d_in[25];
    const float* ln_g = (const float*)d_in[26];
    const float* ln_b = (const float*)d_in[27];

    float* buf = nullptr;
    cudaGetSymbolAddress((void**)&buf, g_scratch);
    auto S  = [&](int s) { return buf + (size_t)s * SLOT; };
    float* wbase = buf + 19 * SLOT;
    auto WB = [&](int w) { return (const float*)(wbase + (size_t)w * WSLOT); };

    // one-time side stream + events (created outside graph capture: the
    // correctness run happens before capture)
    static cudaStream_t s_side = nullptr;
    static cudaEvent_t ev_fork = nullptr, ev_join = nullptr;
    if (s_side == nullptr) {
        cudaStreamCreateWithFlags(&s_side, cudaStreamNonBlocking);
        cudaEventCreateWithFlags(&ev_fork, cudaEventDisableTiming);
        cudaEventCreateWithFlags(&ev_join, cudaEventDisableTiming);
        cudaFuncSetAttribute((const void*)gemm_mma_kernel,
                             cudaFuncAttributeMaxDynamicSharedMemorySize, GEMM_SMEM);
    }

    const int EW_BLOCKS = MROWS * C_ / 4 / 256;   // 4096
    dim3 gg(C_ / BNG, MROWS / BMG);               // (8, 32)

    // K1: fused mix + weight-convert (one launch)
    Ptr12 ws;
    ws.p[0] = Wr;  ws.p[1] = Wk;  ws.p[2] = Wv;  ws.p[3] = W1;
    ws.p[4] = A1;  ws.p[5] = V1;  ws.p[6] = Wg1; ws.p[7] = W2;
    ws.p[8] = A2;  ws.p[9] = V2;  ws.p[10] = Wg2; ws.p[11] = Wo;
    mix_wcvt_kernel<<<MIX_BLOCKS + WCV_BLOCKS, 256>>>(
        x, tm_r, tm_w, tm_k, tm_v, tm_a, tm_g, ws, buf, wbase);

    // Stage-1 batched GEMMs (7)
    GemmBatch7 b1;
    b1.it[0] = { S(0), WB(0), S(6),  0 };   // r
    b1.it[1] = { S(2), WB(1), S(7),  0 };   // k
    b1.it[2] = { S(3), WB(2), S(8),  0 };   // v
    b1.it[3] = { S(1), WB(3), S(9),  1 };   // w1 = tanh(.)
    b1.it[4] = { S(4), WB(4), S(10), 3 };   // a1
    b1.it[5] = { S(3), WB(5), S(11), 3 };   // v1
    b1.it[6] = { S(5), WB(6), S(12), 2 };   // g1 = sigmoid(.)
    gemm_mma_kernel<<<dim3(gg.x, gg.y, 7), 128, GEMM_SMEM>>>(b1);

    // fork: side stream computes g = g1 @ Wg2^T concurrent with b2/ew2/wkv
    cudaEventRecord(ev_fork, 0);
    cudaStreamWaitEvent(s_side, ev_fork, 0);
    GemmBatch7 bg;
    bg.it[0] = { S(12), WB(10), S(16), 0 };
    gemm_mma_kernel<<<dim3(gg.x, gg.y, 1), 128, GEMM_SMEM, s_side>>>(bg);
    cudaEventRecord(ev_join, s_side);

    // Stage-2 batched GEMMs (3), plain outputs
    GemmBatch7 b2;
    b2.it[0] = { S(9),  WB(7), S(13), 0 };
    b2.it[1] = { S(10), WB(8), S(14), 0 };
    b2.it[2] = { S(11), WB(9), S(15), 0 };
    gemm_mma_kernel<<<dim3(gg.x, gg.y, 3), 128, GEMM_SMEM>>>(b2);

    // K5: w decay, k adjust, v blend
    ew2_kernel<<<EW_BLOCKS, 256>>>(S(13), S(14), S(15), S(7), S(8), v_first,
                                   w0, a0, v0, k_a);

    // K6: WKV scan -> y
    wkv_kernel<<<128, 128>>>(S(6), S(13), S(7), S(8), S(17));

    // join side stream (g must be ready for ln_gate)
    cudaStreamWaitEvent(0, ev_join, 0);

    // K7: LN + rkv + gate -> z, tf32-rounded
    ln_gate_kernel<<<MROWS, 256>>>(S(17), S(6), S(7), S(8), S(16),
                                   r_k, ln_g, ln_b, S(18));

    // Final GEMM: out = z @ Wo^T
    GemmBatch7 b3;
    b3.it[0] = { S(18), WB(11), (float*)d_out, 0 };
    gemm_mma_kernel<<<dim3(gg.x, gg.y, 1), 128, GEMM_SMEM>>>(b3);
}